// round 2
// baseline (speedup 1.0000x reference)
#include <cuda_runtime.h>
#include <math.h>

#define BATCH 8192
#define NKNOT 2000
#define NI    1999
#define NT    500
#define NH1   50
#define NH2   10
#define HALO  12
#define CSZ   33
#define NCH   61      // ceil(2000/33)
#define ROWS  4
#define RB    32
#define SSTR  2001    // padded smem row stride (odd -> conflict avoidance)

// ---------------- device scratch (static: allocation-free contract) ----------
__device__ float g_hr[NI];
__device__ float g_w[NI];           // 3*hr^2
__device__ float g_cp[NKNOT];       // Thomas cp_i
__device__ float g_e[NKNOT];        // l_i * inv_m_i   (forward decay factor)
__device__ float g_g[NKNOT];        // inv_m_i
__device__ int   g_pj[NT];
__device__ float g_fj[NT];
__device__ float g_out[(size_t)BATCH * NT];   // 16.4 MB staging (outputs matrix)

__device__ __forceinline__ float tknot(int i) {
    // mimic float32 linspace(0,1,2000): i*step, endpoint forced to 1.0
    return (i >= NI) ? 1.0f : (float)i * (1.0f / 1999.0f);
}

// ---------------- K0: coefficients + eval-point preprocessing ----------------
__global__ void init_kernel(const float* __restrict__ raw_index) {
    const int tid = threadIdx.x;

    for (int i = tid; i < NI; i += blockDim.x) {
        float hr = 1.0f / (tknot(i + 1) - tknot(i));
        g_hr[i] = hr;
        g_w[i]  = 3.0f * hr * hr;
    }

    // cp / inv_m / e: chunk of 8 per thread with 16-halo (contraction ~0.072/step)
    {
        int c0 = tid * 8;
        if (c0 < NKNOT) {
            int c1 = min(c0 + 8, NKNOT);
            int s  = max(0, c0 - 16);
            float cp = 0.26794919243112270f;   // 2 - sqrt(3), fixed point
            for (int i = s; i < c1; i++) {
                float hi   = (i < NI) ? 1.0f / (tknot(i + 1) - tknot(i)) : 0.0f;
                float him1 = (i > 0)  ? 1.0f / (tknot(i) - tknot(i - 1)) : 0.0f;
                float dd   = 2.0f * (him1 + hi);   // boundaries handled (terms vanish)
                float m    = dd - him1 * cp;        // i==0: him1=0 -> seed irrelevant
                float invm = 1.0f / m;
                cp = hi * invm;                     // i==NI-? : u_{1999}=0 -> cp=0
                if (i >= c0) { g_cp[i] = cp; g_g[i] = invm; g_e[i] = him1 * invm; }
            }
        }
    }

    // eval points: t = sigmoid(raw_index); idx = searchsorted(times,t,'left')-1 clip
    for (int j = tid; j < NT; j += blockDim.x) {
        float z = raw_index[j];
        float t = 1.0f / (1.0f + expf(-z));
        int p = (int)(t * 1999.0f);
        if (p < 0) p = 0;
        if (p > 1998) p = 1998;
        while (p < 1998 && tknot(p + 1) < t) p++;
        while (p > 0 && tknot(p) >= t) p--;
        g_pj[j] = p;
        g_fj[j] = t - tknot(p);
    }
}

// ---------------- K1: fused spline solve + evaluate --------------------------
__global__ void spline_kernel(const float* __restrict__ x) {
    extern __shared__ float sm[];
    float* sx  = sm;                 // ROWS * SSTR
    float* skd = sm + ROWS * SSTR;   // ROWS * SSTR
    const int b0  = blockIdx.x * ROWS;
    const int tid = threadIdx.x;

    // stage 4 rows, coalesced float4
    for (int idx = tid; idx < ROWS * (NKNOT / 4); idx += blockDim.x) {
        int rr = idx / (NKNOT / 4), q = idx % (NKNOT / 4);
        float4 v = reinterpret_cast<const float4*>(x + (size_t)(b0 + rr) * NKNOT)[q];
        float* d = sx + rr * SSTR + q * 4;
        d[0] = v.x; d[1] = v.y; d[2] = v.z; d[3] = v.w;
    }
    __syncthreads();

    // chunked Thomas solve with halo (contraction 2-sqrt(3) per step)
    if (tid < NCH * ROWS) {
        const int ch = tid % NCH;          // chunk-major: warp 0 = 32 chunks of row 0
        const int rr = tid / NCH;
        const int c0 = ch * CSZ;
        const int c1 = min(c0 + CSZ, NKNOT);
        const float* xr = sx + rr * SSTR;
        float* kr = skd + rr * SSTR;

        int s = max(0, c0 - HALO);
        float dp = 0.0f;
        float pprev = (s > 0) ? g_w[s - 1] * (xr[s] - xr[s - 1]) : 0.0f;
        for (int i = s; i < c1; i++) {
            float pcur = (i < NI) ? g_w[i] * (xr[i + 1] - xr[i]) : 0.0f;
            float r = pprev + pcur;
            dp = r * g_g[i] - g_e[i] * dp;
            if (i >= c0) kr[i] = dp;
            pprev = pcur;
        }
        // right halo dp kept in registers
        float halo[HALO];
        #pragma unroll
        for (int k = 0; k < HALO; k++) {
            int i = c1 + k;
            if (i < NKNOT) {
                float pcur = (i < NI) ? g_w[i] * (xr[i + 1] - xr[i]) : 0.0f;
                float r = pprev + pcur;
                dp = r * g_g[i] - g_e[i] * dp;
                halo[k] = dp;
                pprev = pcur;
            } else halo[k] = 0.0f;
        }
        // backward sweep
        float xn = 0.0f;
        #pragma unroll
        for (int k = HALO - 1; k >= 0; k--) {
            int i = c1 + k;
            if (i < NKNOT) xn = halo[k] - g_cp[i] * xn;
        }
        for (int i = c1 - 1; i >= c0; i--) {
            xn = kr[i] - g_cp[i] * xn;
            kr[i] = xn;
        }
    }
    __syncthreads();

    // evaluate 500 points per row; consecutive tid -> consecutive j (coalesced store)
    for (int it = tid; it < ROWS * NT; it += blockDim.x) {
        int rr = it / NT, j = it % NT;
        int   p   = g_pj[j];
        float f   = g_fj[j];
        float hrp = g_hr[p];
        const float* xr = sx  + rr * SSTR;
        const float* kr = skd + rr * SSTR;
        float a   = xr[p];
        float dP  = xr[p + 1] - a;
        float kd0 = kr[p], kd1 = kr[p + 1];
        float s6      = 6.0f * dP * hrp;
        float two_c   = (s6 - 4.0f * kd0 - 2.0f * kd1) * hrp;
        float three_d = (3.0f * (kd0 + kd1) - s6) * (hrp * hrp);
        float inner = 0.5f * two_c + three_d * f / 3.0f;
        inner = kd0 + inner * f;
        g_out[(size_t)(b0 + rr) * NT + j] = a + inner * f;
    }
}

// ---------------- K2: fused MLP 500->50->10->1 --------------------------------
__global__ void mlp_kernel(const float* __restrict__ W1, const float* __restrict__ b1,
                           const float* __restrict__ W2, const float* __restrict__ b2,
                           const float* __restrict__ W3, const float* __restrict__ b3,
                           float* __restrict__ out) {
    extern __shared__ float sm[];
    float* sW1 = sm;                   // 500*50
    float* sh1 = sm + NT * NH1;        // RB*50
    float* sh2 = sh1 + RB * NH1;       // RB*10
    const int r0  = blockIdx.x * RB;
    const int tid = threadIdx.x;

    for (int i = tid; i < (NT * NH1) / 4; i += blockDim.x) {
        float4 v = reinterpret_cast<const float4*>(W1)[i];
        sW1[4 * i + 0] = v.x; sW1[4 * i + 1] = v.y;
        sW1[4 * i + 2] = v.z; sW1[4 * i + 3] = v.w;
    }
    __syncthreads();

    for (int pid = tid; pid < RB * NH1; pid += blockDim.x) {
        int r = pid / NH1, k = pid % NH1;
        const float* orow = g_out + (size_t)(r0 + r) * NT;
        float a0 = 0.f, a1 = 0.f, a2 = 0.f, a3 = 0.f;
        for (int j = 0; j < NT; j += 4) {
            a0 = fmaf(orow[j + 0], sW1[(j + 0) * NH1 + k], a0);
            a1 = fmaf(orow[j + 1], sW1[(j + 1) * NH1 + k], a1);
            a2 = fmaf(orow[j + 2], sW1[(j + 2) * NH1 + k], a2);
            a3 = fmaf(orow[j + 3], sW1[(j + 3) * NH1 + k], a3);
        }
        float h = (a0 + a1) + (a2 + a3) + b1[k];
        sh1[pid] = (h >= 0.0f) ? h : 0.01f * h;
    }
    __syncthreads();

    for (int pid = tid; pid < RB * NH2; pid += blockDim.x) {
        int r = pid / NH2, kk = pid % NH2;
        float acc = b2[kk];
        #pragma unroll
        for (int k = 0; k < NH1; k++)
            acc = fmaf(sh1[r * NH1 + k], W2[k * NH2 + kk], acc);
        sh2[pid] = (acc >= 0.0f) ? acc : 0.01f * acc;
    }
    __syncthreads();

    if (tid < RB) {
        float acc = b3[0];
        #pragma unroll
        for (int kk = 0; kk < NH2; kk++)
            acc = fmaf(sh2[tid * NH2 + kk], W3[kk], acc);
        out[r0 + tid] = acc;
    }
}

// ---------------- launch ------------------------------------------------------
extern "C" void kernel_launch(void* const* d_in, const int* in_sizes, int n_in,
                              void* d_out, int out_size) {
    const float* x  = (const float*)d_in[0];
    const float* ri = (const float*)d_in[1];
    const float* W1 = (const float*)d_in[2];
    const float* b1 = (const float*)d_in[3];
    const float* W2 = (const float*)d_in[4];
    const float* b2 = (const float*)d_in[5];
    const float* W3 = (const float*)d_in[6];
    const float* b3 = (const float*)d_in[7];
    float* out = (float*)d_out;

    size_t smem1 = (size_t)2 * ROWS * SSTR * sizeof(float);              // 64,032 B
    size_t smem2 = (size_t)(NT * NH1 + RB * NH1 + RB * NH2) * sizeof(float); // 107,680 B
    cudaFuncSetAttribute(spline_kernel, cudaFuncAttributeMaxDynamicSharedMemorySize, (int)smem1);
    cudaFuncSetAttribute(mlp_kernel,    cudaFuncAttributeMaxDynamicSharedMemorySize, (int)smem2);

    init_kernel<<<1, 256>>>(ri);
    spline_kernel<<<BATCH / ROWS, 256, smem1>>>(x);
    mlp_kernel<<<BATCH / RB, 256, smem2>>>(W1, b1, W2, b2, W3, b3, out);
}

// round 3
// speedup vs baseline: 1.8696x; 1.8696x over previous
#include <cuda_runtime.h>
#include <math.h>

#define BATCH 8192
#define NKNOT 2000
#define NI    1999
#define NT    500
#define NH1   50
#define NH2   10
#define HALO  12
#define CSZ   33
#define NCH   61      // ceil(2000/33)
#define ROWS  4
#define RB    32
#define SSTR  2001    // padded smem row stride

// Thomas-recurrence constants for the uniform knot grid (data-independent).
// cp_{i+1} = 1/(4 - cp_i), cp_0 = 0.5; converged to fp32 by i=8.
__constant__ float CP_TAB[8] = {
    0.5f, 0.28571429f, 0.26923077f, 0.26804124f,
    0.26795580f, 0.26794967f, 0.26794923f, 0.26794919f
};
#define CSTAR  0.26794919f            // 2 - sqrt(3)
#define ELAST  0.57735027f            // 1/(2 - CSTAR) = 1/sqrt(3)
#define PW     5997.0f                // 3 * 1999   (= W*h, W = 3*hr^2, h = 1/1999)
#define WGC    (PW * CSTAR)           // interior: r*g = (x[i+1]-x[i-1]) * WGC
#define WGL    (PW * ELAST)           // i = 1999 edge factor

// ---------------- device scratch (allocation-free contract) ------------------
__device__ int    g_pj[NT];
__device__ float4 g_ev[NT];                     // folded cubic coefficients per eval pt
__device__ float  g_out[(size_t)BATCH * NT];    // 16.4 MB staging

__device__ __forceinline__ float tknot(int i) {
    return (i >= NI) ? 1.0f : (float)i * (1.0f / 1999.0f);
}

// ---------------- K0: eval-point preprocessing (fully parallel) --------------
__global__ void init_kernel(const float* __restrict__ raw_index) {
    int j = blockIdx.x * blockDim.x + threadIdx.x;
    if (j >= NT) return;
    float z = raw_index[j];
    float t = 1.0f / (1.0f + expf(-z));
    int p = (int)(t * 1999.0f);
    if (p < 0) p = 0;
    if (p > 1998) p = 1998;
    while (p < 1998 && tknot(p + 1) < t) p++;
    while (p > 0 && tknot(p) >= t) p--;

    float tp  = tknot(p);
    float tp1 = tknot(p + 1);
    float Hh  = tp1 - tp;
    float u   = (t - tp) / Hh;
    // result = x[p]*q0 + x[p+1]*q1 + kd[p]*c0 + kd[p+1]*c1   (Hermite form)
    float cb  = u * u * (3.0f - 2.0f * u);
    float omu = 1.0f - u;
    float4 c;
    c.x = 1.0f - cb;
    c.y = cb;
    c.z = Hh * u * omu * omu;
    c.w = Hh * u * u * (u - 1.0f);
    g_pj[j] = p;
    g_ev[j] = c;
}

// ---------------- K1: fused spline solve + evaluate --------------------------
__global__ void spline_kernel(const float* __restrict__ x) {
    extern __shared__ float sm[];
    float* sx  = sm;                 // ROWS * SSTR
    float* skd = sm + ROWS * SSTR;   // ROWS * SSTR
    const int b0  = blockIdx.x * ROWS;
    const int tid = threadIdx.x;

    // stage 4 rows, coalesced float4
    for (int idx = tid; idx < ROWS * (NKNOT / 4); idx += blockDim.x) {
        int rr = idx / (NKNOT / 4), q = idx % (NKNOT / 4);
        float4 v = reinterpret_cast<const float4*>(x + (size_t)(b0 + rr) * NKNOT)[q];
        float* d = sx + rr * SSTR + q * 4;
        d[0] = v.x; d[1] = v.y; d[2] = v.z; d[3] = v.w;
    }
    __syncthreads();

    // chunked Thomas solve, constants only (no global table loads)
    if (tid < NCH * ROWS) {
        const int ch = tid % NCH;
        const int rr = tid / NCH;
        const int c0 = ch * CSZ;
        const int c1 = min(c0 + CSZ, NKNOT);
        const float* xr = sx + rr * SSTR;
        float* kr = skd + rr * SSTR;

        float dp = 0.0f;
        float xm, xc;

        if (ch == 0) {
            // generic forward over [0, 33): first 8 coefficients from table
            float pp = 0.0f;
            xc = xr[0];
            for (int i = 0; i < CSZ; i++) {
                float xp = xr[i + 1];
                float pc = PW * (xp - xc);
                float cp = (i < 8) ? CP_TAB[i] : CSTAR;
                float e  = (i == 0) ? 0.0f : cp;
                dp = cp * (pp + pc) - e * dp;
                kr[i] = dp;
                pp = pc; xc = xp;
            }
            xm = xr[CSZ - 1];        // xc == xr[CSZ]
        } else {
            // left halo (constants valid: s >= 21)
            int s = c0 - HALO;
            xm = xr[s - 1];
            xc = xr[s];
            for (int i = s; i < c0; i++) {
                float xp = xr[i + 1];
                dp = fmaf(-CSTAR, dp, (xp - xm) * WGC);
                xm = xc; xc = xp;
            }
            int e_end = (c1 == NKNOT) ? NI : c1;
            for (int i = c0; i < e_end; i++) {
                float xp = xr[i + 1];
                dp = fmaf(-CSTAR, dp, (xp - xm) * WGC);
                kr[i] = dp;
                xm = xc; xc = xp;
            }
            if (c1 == NKNOT) {       // i = 1999 boundary step (pcur = 0)
                dp = fmaf(-ELAST, dp, (xc - xm) * WGL);
                kr[NI] = dp;
            }
        }

        // right halo in registers (interior constants; skipped for last chunk)
        float halo[HALO];
        if (c1 < NKNOT) {
            #pragma unroll
            for (int k = 0; k < HALO; k++) {
                int i = c1 + k;
                float xp = xr[i + 1];
                dp = fmaf(-CSTAR, dp, (xp - xm) * WGC);
                halo[k] = dp;
                xm = xc; xc = xp;
            }
        }

        // backward sweep
        float xn = 0.0f;
        int i = c1 - 1;
        if (c1 < NKNOT) {
            #pragma unroll
            for (int k = HALO - 1; k >= 0; k--)
                xn = fmaf(-CSTAR, xn, halo[k]);
        } else {                     // chunk 60: cp[1999] = 0
            xn = kr[NI];
            i = NI - 1;
        }
        if (ch == 0) {
            for (; i >= 0; i--) {
                float cp = (i < 8) ? CP_TAB[i] : CSTAR;
                xn = kr[i] - cp * xn;
                kr[i] = xn;
            }
        } else {
            for (; i >= c0; i--) {
                xn = fmaf(-CSTAR, xn, kr[i]);
                kr[i] = xn;
            }
        }
    }
    __syncthreads();

    // evaluate 500 points per row (4 FMA each, folded coefficients)
    for (int it = tid; it < ROWS * NT; it += blockDim.x) {
        int rr = it / NT, j = it % NT;
        int    p = g_pj[j];
        float4 c = g_ev[j];
        const float* xr = sx  + rr * SSTR;
        const float* kr = skd + rr * SSTR;
        float res = xr[p] * c.x;
        res = fmaf(xr[p + 1], c.y, res);
        res = fmaf(kr[p],     c.z, res);
        res = fmaf(kr[p + 1], c.w, res);
        g_out[(size_t)(b0 + rr) * NT + j] = res;
    }
}

// ---------------- K2: fused MLP 500->50->10->1 --------------------------------
__global__ void mlp_kernel(const float* __restrict__ W1, const float* __restrict__ b1,
                           const float* __restrict__ W2, const float* __restrict__ b2,
                           const float* __restrict__ W3, const float* __restrict__ b3,
                           float* __restrict__ out) {
    extern __shared__ float sm[];
    float* sW1 = sm;                   // 500*50
    float* sh1 = sm + NT * NH1;        // RB*50
    float* sh2 = sh1 + RB * NH1;       // RB*10
    const int r0  = blockIdx.x * RB;
    const int tid = threadIdx.x;

    for (int i = tid; i < (NT * NH1) / 4; i += blockDim.x) {
        float4 v = reinterpret_cast<const float4*>(W1)[i];
        sW1[4 * i + 0] = v.x; sW1[4 * i + 1] = v.y;
        sW1[4 * i + 2] = v.z; sW1[4 * i + 3] = v.w;
    }
    __syncthreads();

    // layer 1: each thread computes 2 adjacent k for one row
    for (int pid = tid; pid < RB * (NH1 / 2); pid += blockDim.x) {
        int r  = pid / (NH1 / 2);
        int k0 = (pid % (NH1 / 2)) * 2;
        const float4* o4 = reinterpret_cast<const float4*>(g_out + (size_t)(r0 + r) * NT);
        float a0 = 0.f, a1 = 0.f;
        for (int j4 = 0; j4 < NT / 4; j4++) {
            float4 o = o4[j4];
            const float* wb = sW1 + (j4 * 4) * NH1 + k0;
            float2 w0 = *reinterpret_cast<const float2*>(wb);
            float2 w1 = *reinterpret_cast<const float2*>(wb + NH1);
            float2 w2 = *reinterpret_cast<const float2*>(wb + 2 * NH1);
            float2 w3 = *reinterpret_cast<const float2*>(wb + 3 * NH1);
            a0 = fmaf(o.x, w0.x, a0); a1 = fmaf(o.x, w0.y, a1);
            a0 = fmaf(o.y, w1.x, a0); a1 = fmaf(o.y, w1.y, a1);
            a0 = fmaf(o.z, w2.x, a0); a1 = fmaf(o.z, w2.y, a1);
            a0 = fmaf(o.w, w3.x, a0); a1 = fmaf(o.w, w3.y, a1);
        }
        float h0 = a0 + b1[k0];
        float h1 = a1 + b1[k0 + 1];
        sh1[r * NH1 + k0]     = (h0 >= 0.0f) ? h0 : 0.01f * h0;
        sh1[r * NH1 + k0 + 1] = (h1 >= 0.0f) ? h1 : 0.01f * h1;
    }
    __syncthreads();

    for (int pid = tid; pid < RB * NH2; pid += blockDim.x) {
        int r = pid / NH2, kk = pid % NH2;
        float acc = b2[kk];
        #pragma unroll
        for (int k = 0; k < NH1; k++)
            acc = fmaf(sh1[r * NH1 + k], W2[k * NH2 + kk], acc);
        sh2[pid] = (acc >= 0.0f) ? acc : 0.01f * acc;
    }
    __syncthreads();

    if (tid < RB) {
        float acc = b3[0];
        #pragma unroll
        for (int kk = 0; kk < NH2; kk++)
            acc = fmaf(sh2[tid * NH2 + kk], W3[kk], acc);
        out[r0 + tid] = acc;
    }
}

// ---------------- launch ------------------------------------------------------
extern "C" void kernel_launch(void* const* d_in, const int* in_sizes, int n_in,
                              void* d_out, int out_size) {
    const float* x  = (const float*)d_in[0];
    const float* ri = (const float*)d_in[1];
    const float* W1 = (const float*)d_in[2];
    const float* b1 = (const float*)d_in[3];
    const float* W2 = (const float*)d_in[4];
    const float* b2 = (const float*)d_in[5];
    const float* W3 = (const float*)d_in[6];
    const float* b3 = (const float*)d_in[7];
    float* out = (float*)d_out;

    size_t smem1 = (size_t)2 * ROWS * SSTR * sizeof(float);                  // 64,032 B
    size_t smem2 = (size_t)(NT * NH1 + RB * NH1 + RB * NH2) * sizeof(float); // 107,680 B
    cudaFuncSetAttribute(spline_kernel, cudaFuncAttributeMaxDynamicSharedMemorySize, (int)smem1);
    cudaFuncSetAttribute(mlp_kernel,    cudaFuncAttributeMaxDynamicSharedMemorySize, (int)smem2);

    init_kernel<<<2, 256>>>(ri);
    spline_kernel<<<BATCH / ROWS, 256, smem1>>>(x);
    mlp_kernel<<<BATCH / RB, 256, smem2>>>(W1, b1, W2, b2, W3, b3, out);
}

// round 4
// speedup vs baseline: 3.0336x; 1.6226x over previous
#include <cuda_runtime.h>
#include <math.h>

#define BATCH 8192
#define NKNOT 2000
#define NI    1999
#define NT    500
#define NH1   50
#define NH2   10
#define HALO  12
#define CSZ   33
#define NCH   61
#define ROWS  4
#define SSTR  2001

// ---- MLP config ----
#define MROWS 64                 // rows per MLP block
#define NGRP  16                 // 4-row groups per MLP block
#define GSTR  2020               // act group stride in floats (bank spread: 2*GSTR mod 32 = 8)
#define NSEG  6                  // j-split
#define TILES 80                 // (64/8 row-tiles) * (50/5 k-tiles)
#define ACT_FL    (NGRP * GSTR)          // 32320 floats
#define W1T_OFF   ACT_FL                 // W1T at float offset 32320
#define W1T_FL    (NH1 * NT)             // 25000 floats
#define CONST_OFF (W1T_OFF + W1T_FL)     // 57320
#define SMEM_MLP_FL (CONST_OFF + 576)    // 57896 floats = 231584 B

// Thomas-recurrence constants (uniform grid, data-independent)
__constant__ float CP_TAB[8] = {
    0.5f, 0.28571429f, 0.26923077f, 0.26804124f,
    0.26795580f, 0.26794967f, 0.26794923f, 0.26794919f
};
#define CSTAR  0.26794919f
#define ELAST  0.57735027f
#define PW     5997.0f
#define WGC    (PW * CSTAR)
#define WGL    (PW * ELAST)

// ---------------- device scratch ----------------
__device__ int    g_pj[NT];
__device__ float4 g_ev[NT];
__device__ float  g_out4[(size_t)BATCH * NT];   // blocked: [2048][500][4]
__device__ float  g_W1T[NH1 * NT];              // transposed W1 [k][j]

__device__ __forceinline__ float tknot(int i) {
    return (i >= NI) ? 1.0f : (float)i * (1.0f / 1999.0f);
}

__device__ __forceinline__ void ffma2(unsigned long long& acc,
                                      unsigned long long a, unsigned long long b) {
    asm("fma.rn.f32x2 %0, %1, %2, %0;" : "+l"(acc) : "l"(a), "l"(b));
}
__device__ __forceinline__ unsigned long long pack2(float w) {
    unsigned long long r;
    asm("mov.b64 %0, {%1, %1};" : "=l"(r) : "f"(w));
    return r;
}
__device__ __forceinline__ void unpack2(unsigned long long v, float& lo, float& hi) {
    asm("mov.b64 {%0, %1}, %2;" : "=f"(lo), "=f"(hi) : "l"(v));
}

// ---------------- K0: eval points + W1 transpose ----------------
__global__ void init_kernel(const float* __restrict__ raw_index,
                            const float* __restrict__ W1) {
    int gtid = blockIdx.x * 256 + threadIdx.x;
    if (blockIdx.x < 2) {
        int j = gtid;
        if (j >= NT) return;
        float z = raw_index[j];
        float t = 1.0f / (1.0f + expf(-z));
        int p = (int)(t * 1999.0f);
        if (p < 0) p = 0;
        if (p > 1998) p = 1998;
        while (p < 1998 && tknot(p + 1) < t) p++;
        while (p > 0 && tknot(p) >= t) p--;
        float tp  = tknot(p);
        float Hh  = tknot(p + 1) - tp;
        float u   = (t - tp) / Hh;
        float cb  = u * u * (3.0f - 2.0f * u);
        float omu = 1.0f - u;
        float4 c;
        c.x = 1.0f - cb;
        c.y = cb;
        c.z = Hh * u * omu * omu;
        c.w = Hh * u * u * (u - 1.0f);
        g_pj[j] = p;
        g_ev[j] = c;
    } else {
        int idx = gtid - 512;
        if (idx < NT * NH1) {
            int j = idx / NH1, k = idx % NH1;
            g_W1T[k * NT + j] = W1[idx];
        }
    }
}

// ---------------- K1: fused spline solve + evaluate ----------------
__global__ void spline_kernel(const float* __restrict__ x) {
    extern __shared__ float sm[];
    float* sx  = sm;
    float* skd = sm + ROWS * SSTR;
    const int b0  = blockIdx.x * ROWS;
    const int tid = threadIdx.x;

    for (int idx = tid; idx < ROWS * (NKNOT / 4); idx += blockDim.x) {
        int rr = idx / (NKNOT / 4), q = idx % (NKNOT / 4);
        float4 v = reinterpret_cast<const float4*>(x + (size_t)(b0 + rr) * NKNOT)[q];
        float* d = sx + rr * SSTR + q * 4;
        d[0] = v.x; d[1] = v.y; d[2] = v.z; d[3] = v.w;
    }
    __syncthreads();

    if (tid < NCH * ROWS) {
        const int ch = tid % NCH;
        const int rr = tid / NCH;
        const int c0 = ch * CSZ;
        const int c1 = min(c0 + CSZ, NKNOT);
        const float* xr = sx + rr * SSTR;
        float* kr = skd + rr * SSTR;

        float dp = 0.0f;
        float xm, xc;

        if (ch == 0) {
            float pp = 0.0f;
            xc = xr[0];
            for (int i = 0; i < CSZ; i++) {
                float xp = xr[i + 1];
                float pc = PW * (xp - xc);
                float cp = (i < 8) ? CP_TAB[i] : CSTAR;
                float e  = (i == 0) ? 0.0f : cp;
                dp = cp * (pp + pc) - e * dp;
                kr[i] = dp;
                pp = pc; xc = xp;
            }
            xm = xr[CSZ - 1];
        } else {
            int s = c0 - HALO;
            xm = xr[s - 1];
            xc = xr[s];
            for (int i = s; i < c0; i++) {
                float xp = xr[i + 1];
                dp = fmaf(-CSTAR, dp, (xp - xm) * WGC);
                xm = xc; xc = xp;
            }
            int e_end = (c1 == NKNOT) ? NI : c1;
            for (int i = c0; i < e_end; i++) {
                float xp = xr[i + 1];
                dp = fmaf(-CSTAR, dp, (xp - xm) * WGC);
                kr[i] = dp;
                xm = xc; xc = xp;
            }
            if (c1 == NKNOT) {
                dp = fmaf(-ELAST, dp, (xc - xm) * WGL);
                kr[NI] = dp;
            }
        }

        float halo[HALO];
        if (c1 < NKNOT) {
            #pragma unroll
            for (int k = 0; k < HALO; k++) {
                int i = c1 + k;
                float xp = xr[i + 1];
                dp = fmaf(-CSTAR, dp, (xp - xm) * WGC);
                halo[k] = dp;
                xm = xc; xc = xp;
            }
        }

        float xn = 0.0f;
        int i = c1 - 1;
        if (c1 < NKNOT) {
            #pragma unroll
            for (int k = HALO - 1; k >= 0; k--)
                xn = fmaf(-CSTAR, xn, halo[k]);
        } else {
            xn = kr[NI];
            i = NI - 1;
        }
        if (ch == 0) {
            for (; i >= 0; i--) {
                float cp = (i < 8) ? CP_TAB[i] : CSTAR;
                xn = kr[i] - cp * xn;
                kr[i] = xn;
            }
        } else {
            for (; i >= c0; i--) {
                xn = fmaf(-CSTAR, xn, kr[i]);
                kr[i] = xn;
            }
        }
    }
    __syncthreads();

    // evaluate; blocked output layout [block][j][4rows] -> contiguous in tid
    float* ob = g_out4 + (size_t)blockIdx.x * (ROWS * NT);
    for (int it = tid; it < ROWS * NT; it += blockDim.x) {
        int j  = it >> 2;
        int rr = it & 3;
        int    p = g_pj[j];
        float4 c = g_ev[j];
        const float* xr = sx  + rr * SSTR;
        const float* kr = skd + rr * SSTR;
        float res = xr[p] * c.x;
        res = fmaf(xr[p + 1], c.y, res);
        res = fmaf(kr[p],     c.z, res);
        res = fmaf(kr[p + 1], c.w, res);
        ob[it] = res;
    }
}

// ---------------- K2: blocked weight-stationary MLP ----------------
__global__ __launch_bounds__(512, 1)
void mlp_kernel(const float* __restrict__ b1,
                const float* __restrict__ W2, const float* __restrict__ b2,
                const float* __restrict__ W3, const float* __restrict__ b3,
                float* __restrict__ out) {
    extern __shared__ float sm[];
    float* sact = sm;                    // 16 groups x 2020 floats
    float* sw1t = sm + W1T_OFF;          // [k][j] 50x500
    float* scst = sm + CONST_OFF;        // W2(500) b1(50) b2(10) W3(10) b3(1)
    const int tid = threadIdx.x;
    const int b   = blockIdx.x;

    // stage activations (straight copy, coalesced, conflict-free)
    {
        const float4* src = (const float4*)(g_out4 + (size_t)b * NGRP * (ROWS * NT));
        for (int i = tid; i < NGRP * 500; i += 512) {
            int g = i / 500, p = i % 500;
            float4 v = src[i];
            float* d = sact + g * GSTR + p * 4;
            d[0] = v.x; d[1] = v.y; d[2] = v.z; d[3] = v.w;
        }
    }
    // stage W1T (straight copy)
    {
        const float4* w4 = (const float4*)g_W1T;
        for (int i = tid; i < W1T_FL / 4; i += 512) {
            float4 v = w4[i];
            float* d = sw1t + i * 4;
            d[0] = v.x; d[1] = v.y; d[2] = v.z; d[3] = v.w;
        }
    }
    // stage small constants
    for (int i = tid; i < NH1 * NH2; i += 512) scst[i] = W2[i];
    if (tid < NH1) scst[500 + tid] = b1[tid];
    if (tid < NH2) scst[550 + tid] = b2[tid];
    if (tid < NH2) scst[560 + tid] = W3[tid];
    if (tid == 0)  scst[570] = b3[0];
    __syncthreads();

    // ---- layer 1: R=8 rows x K=5 k per thread, FFMA2 row-paired ----
    unsigned long long acc[4][5] = {};
    const bool active = tid < TILES * NSEG;   // 480
    int rt = 0, kt = 0, seg = 0;
    if (active) {
        seg = tid / TILES;
        int tile = tid % TILES;
        rt = tile & 7;
        kt = tile >> 3;
        int j0 = seg * 84;
        int j1 = min(j0 + 84, NT);
        const ulonglong2* oa = (const ulonglong2*)(sact + (2 * rt) * GSTR);
        const ulonglong2* ob = (const ulonglong2*)(sact + (2 * rt + 1) * GSTR);
        const float* wk = sw1t + kt * 5 * NT;
        #pragma unroll 2
        for (int j = j0; j < j1; j++) {
            ulonglong2 a  = oa[j];
            ulonglong2 bb = ob[j];
            #pragma unroll
            for (int kk = 0; kk < 5; kk++) {
                unsigned long long wp = pack2(wk[kk * NT + j]);
                ffma2(acc[0][kk], a.x,  wp);
                ffma2(acc[1][kk], a.y,  wp);
                ffma2(acc[2][kk], bb.x, wp);
                ffma2(acc[3][kk], bb.y, wp);
            }
        }
    }
    __syncthreads();   // all reads of sw1t/sact done

    // write partials over dead W1T area: [seg][row][k]
    float* spart = sm + W1T_OFF;
    if (active) {
        #pragma unroll
        for (int p = 0; p < 4; p++)
            #pragma unroll
            for (int kk = 0; kk < 5; kk++) {
                float lo, hi;
                unpack2(acc[p][kk], lo, hi);
                int row = 8 * rt + 2 * p;
                int k   = kt * 5 + kk;
                spart[seg * (MROWS * NH1) + row * NH1 + k]       = lo;
                spart[seg * (MROWS * NH1) + (row + 1) * NH1 + k] = hi;
            }
    }
    __syncthreads();

    // reduce 6 partials + bias + leaky -> sh1 (overlays dead act area)
    float* sh1 = sm;                       // 64*50
    for (int i = tid; i < MROWS * NH1; i += 512) {
        float s = spart[i];
        #pragma unroll
        for (int q = 1; q < NSEG; q++) s += spart[q * (MROWS * NH1) + i];
        s += scst[500 + (i % NH1)];
        sh1[i] = (s >= 0.0f) ? s : 0.01f * s;
    }
    __syncthreads();

    // layer 2
    float* sh2 = sm + 4096;                // 64*10
    for (int i = tid; i < MROWS * NH2; i += 512) {
        int r = i / NH2, kk = i % NH2;
        float a = scst[550 + kk];
        #pragma unroll
        for (int k = 0; k < NH1; k++)
            a = fmaf(sh1[r * NH1 + k], scst[k * NH2 + kk], a);
        sh2[i] = (a >= 0.0f) ? a : 0.01f * a;
    }
    __syncthreads();

    // layer 3
    if (tid < MROWS) {
        float a = scst[570];
        #pragma unroll
        for (int i = 0; i < NH2; i++)
            a = fmaf(sh2[tid * NH2 + i], scst[560 + i], a);
        out[b * MROWS + tid] = a;
    }
}

// ---------------- launch ----------------
extern "C" void kernel_launch(void* const* d_in, const int* in_sizes, int n_in,
                              void* d_out, int out_size) {
    const float* x  = (const float*)d_in[0];
    const float* ri = (const float*)d_in[1];
    const float* W1 = (const float*)d_in[2];
    const float* b1 = (const float*)d_in[3];
    const float* W2 = (const float*)d_in[4];
    const float* b2 = (const float*)d_in[5];
    const float* W3 = (const float*)d_in[6];
    const float* b3 = (const float*)d_in[7];
    float* out = (float*)d_out;

    size_t smem1 = (size_t)2 * ROWS * SSTR * sizeof(float);   // 64,032 B
    size_t smem2 = (size_t)SMEM_MLP_FL * sizeof(float);       // 231,584 B
    cudaFuncSetAttribute(spline_kernel, cudaFuncAttributeMaxDynamicSharedMemorySize, (int)smem1);
    cudaFuncSetAttribute(mlp_kernel,    cudaFuncAttributeMaxDynamicSharedMemorySize, (int)smem2);

    init_kernel<<<100, 256>>>(ri, W1);
    spline_kernel<<<BATCH / ROWS, 256, smem1>>>(x);
    mlp_kernel<<<BATCH / MROWS, 512, smem2>>>(b1, W2, b2, W3, b3, out);
}

// round 5
// speedup vs baseline: 3.6497x; 1.2031x over previous
#include <cuda_runtime.h>
#include <math.h>

#define BATCH 8192
#define NKNOT 2000
#define NI    1999
#define NT    500
#define NH1   50
#define NH2   10
#define HALO  12
#define CSZ   33
#define NCH   61

// spline smem layout (floats)
#define PSTR      4004                  // per-pair interleaved stride (2 rows x 2000 + pad)
#define SKD_OFF   (2 * PSTR)            // 8008
#define SEV_OFF   (4 * PSTR)            // 16016 (16B aligned: 64064 B)
#define SPJ_OFF   (SEV_OFF + 4 * NT)    // 18016
#define SMEM_SPL_FL (SPJ_OFF + NT)      // 18516 -> 74,064 B (3 blocks/SM)

// MLP config
#define MROWS 64
#define NGRP  16
#define GSTR  2020                       // group stride: 4*rt distinct banks (GSTR mod 32 = 4)
#define W1TS  501                        // padded W1T row stride (conflict-free transpose)
#define NSEG  6
#define TILES 80
#define ACT_FL     (NGRP * GSTR)         // 32320
#define W1T_OFF    ACT_FL
#define W1T_FL     (NH1 * W1TS)          // 25050
#define CONST_OFF  (W1T_OFF + W1T_FL)    // 57370
#define SMEM_MLP_FL (CONST_OFF + 576)    // 57946 -> 231,784 B

// Thomas constants (uniform grid)
__constant__ float CP_TAB[8] = {
    0.5f, 0.28571429f, 0.26923077f, 0.26804124f,
    0.26795580f, 0.26794967f, 0.26794923f, 0.26794919f
};
#define CSTAR  0.26794919f
#define ELAST  0.57735027f
#define PW     5997.0f
#define WGC    (PW * CSTAR)
#define WGL    (PW * ELAST)

typedef unsigned long long ull;

__device__ float g_out[(size_t)BATCH * NT];   // blocked [2048 blk][500 j][4 rows]

// ---- f32x2 helpers (Blackwell packed fp32; only reachable via PTX) ----
__device__ __forceinline__ ull f2fma(ull a, ull b, ull c) {
    ull d; asm("fma.rn.f32x2 %0, %1, %2, %3;" : "=l"(d) : "l"(a), "l"(b), "l"(c)); return d;
}
__device__ __forceinline__ ull f2mul(ull a, ull b) {
    ull d; asm("mul.rn.f32x2 %0, %1, %2;" : "=l"(d) : "l"(a), "l"(b)); return d;
}
__device__ __forceinline__ ull f2add(ull a, ull b) {
    ull d; asm("add.rn.f32x2 %0, %1, %2;" : "=l"(d) : "l"(a), "l"(b)); return d;
}
__device__ __forceinline__ ull splat(float w) {
    ull r; asm("mov.b64 %0, {%1, %1};" : "=l"(r) : "f"(w)); return r;
}
__device__ __forceinline__ void unpack2(ull v, float& lo, float& hi) {
    asm("mov.b64 {%0, %1}, %2;" : "=f"(lo), "=f"(hi) : "l"(v));
}

__device__ __forceinline__ float tknot(int i) {
    return (i >= NI) ? 1.0f : (float)i * (1.0f / 1999.0f);
}

// =================== K1: fused spline solve + evaluate (f32x2) ===============
__global__ __launch_bounds__(256)
void spline_kernel(const float* __restrict__ x, const float* __restrict__ raw_index) {
    extern __shared__ float sm[];
    float*  sxp  = sm;                          // 2 pairs x PSTR interleaved x
    float*  skdp = sm + SKD_OFF;                // 2 pairs x PSTR interleaved kd
    float4* sev  = (float4*)(sm + SEV_OFF);     // folded Hermite coeffs
    int*    spj  = (int*)(sm + SPJ_OFF);
    const int b0  = blockIdx.x * 4;
    const int tid = threadIdx.x;

    // eval-point preprocessing, per block (cheap; removes init kernel)
    for (int j = tid; j < NT; j += 256) {
        float z = raw_index[j];
        float t = 1.0f / (1.0f + expf(-z));
        int p = (int)(t * 1999.0f);
        if (p < 0) p = 0;
        if (p > 1998) p = 1998;
        while (p < 1998 && tknot(p + 1) < t) p++;
        while (p > 0 && tknot(p) >= t) p--;
        float tp  = tknot(p);
        float Hh  = tknot(p + 1) - tp;
        float u   = (t - tp) / Hh;
        float cb  = u * u * (3.0f - 2.0f * u);
        float omu = 1.0f - u;
        float4 c;
        c.x = 1.0f - cb;
        c.y = cb;
        c.z = Hh * u * omu * omu;
        c.w = Hh * u * u * (u - 1.0f);
        spj[j] = p;
        sev[j] = c;
    }

    // stage 4 rows as 2 interleaved pairs (coalesced LDG.128)
    for (int i = tid; i < 2 * 500; i += 256) {
        int pr = i / 500, q = i % 500;
        const float4* r0 = (const float4*)(x + (size_t)(b0 + 2 * pr)     * NKNOT);
        const float4* r1 = (const float4*)(x + (size_t)(b0 + 2 * pr + 1) * NKNOT);
        float4 a = r0[q], b = r1[q];
        float4* d = (float4*)(sxp + pr * PSTR + q * 8);
        d[0] = make_float4(a.x, b.x, a.y, b.y);
        d[1] = make_float4(a.z, b.z, a.w, b.w);
    }
    __syncthreads();

    // chunked Thomas solve, 2 rows per thread via f32x2
    if (tid < 2 * NCH) {
        const int pr = tid / NCH;
        const int ch = tid - pr * NCH;
        const int c0 = ch * CSZ;
        const int c1 = min(c0 + CSZ, NKNOT);
        const ull* X = (const ull*)(sxp  + pr * PSTR);
        ull*       K = (ull*)      (skdp + pr * PSTR);

        const ull NEG1 = splat(-1.0f);
        const ull CW   = splat(WGC);
        const ull CN   = splat(-CSTAR);

        ull dp = 0ULL;
        ull xm, xc;

        if (ch == 0) {
            ull pp = 0ULL;
            xc = X[0];
            for (int i = 0; i < CSZ; i++) {
                ull xp   = X[i + 1];
                ull diff = f2fma(xc, NEG1, xp);
                ull pc   = f2mul(diff, splat(PW));
                ull s    = f2add(pp, pc);
                if (i == 0) dp = f2mul(s, splat(0.5f));
                else {
                    float cp = (i < 8) ? CP_TAB[i] : CSTAR;
                    dp = f2mul(f2fma(dp, NEG1, s), splat(cp));  // cp*(s - dp)
                }
                K[i] = dp;
                pp = pc; xc = xp;
            }
            xm = X[CSZ - 1];
        } else {
            int s0 = c0 - HALO;
            xm = X[s0 - 1]; xc = X[s0];
            for (int i = s0; i < c0; i++) {
                ull xp = X[i + 1];
                dp = f2fma(dp, CN, f2mul(f2fma(xm, NEG1, xp), CW));
                xm = xc; xc = xp;
            }
            int e_end = (c1 == NKNOT) ? NI : c1;
            for (int i = c0; i < e_end; i++) {
                ull xp = X[i + 1];
                dp = f2fma(dp, CN, f2mul(f2fma(xm, NEG1, xp), CW));
                K[i] = dp;
                xm = xc; xc = xp;
            }
            if (c1 == NKNOT) {   // i = 1999 boundary
                dp = f2fma(dp, splat(-ELAST), f2mul(f2fma(xm, NEG1, xc), splat(WGL)));
                K[NI] = dp;
            }
        }

        // right halo in registers
        ull halo[HALO];
        if (c1 < NKNOT) {
            #pragma unroll
            for (int k = 0; k < HALO; k++) {
                ull xp = X[c1 + k + 1];
                dp = f2fma(dp, CN, f2mul(f2fma(xm, NEG1, xp), CW));
                halo[k] = dp;
                xm = xc; xc = xp;
            }
        }

        // backward sweep
        ull xn = 0ULL;
        int i = c1 - 1;
        if (c1 < NKNOT) {
            #pragma unroll
            for (int k = HALO - 1; k >= 0; k--)
                xn = f2fma(xn, CN, halo[k]);
        } else {
            xn = K[NI];
            i = NI - 1;
        }
        if (ch == 0) {
            for (; i >= 0; i--) {
                float cp = (i < 8) ? CP_TAB[i] : CSTAR;
                xn = f2fma(xn, splat(-cp), K[i]);
                K[i] = xn;
            }
        } else {
            for (; i >= c0; i--) {
                xn = f2fma(xn, CN, K[i]);
                K[i] = xn;
            }
        }
    }
    __syncthreads();

    // evaluate: 2 rows per f32x2 item, blocked output [blk][j][4rows]
    float* ob = g_out + (size_t)blockIdx.x * (4 * NT);
    for (int it = tid; it < 2 * NT; it += 256) {
        int j  = it >> 1;
        int pr = it & 1;
        int    p = spj[j];
        float4 c = sev[j];
        const ull* X = (const ull*)(sxp  + pr * PSTR);
        const ull* K = (const ull*)(skdp + pr * PSTR);
        ull r = f2mul(X[p], splat(c.x));
        r = f2fma(X[p + 1], splat(c.y), r);
        r = f2fma(K[p],     splat(c.z), r);
        r = f2fma(K[p + 1], splat(c.w), r);
        *(ull*)(ob + it * 2) = r;
    }
}

// =================== K2: blocked weight-stationary MLP =======================
__global__ __launch_bounds__(512, 1)
void mlp_kernel(const float* __restrict__ W1, const float* __restrict__ b1,
                const float* __restrict__ W2, const float* __restrict__ b2,
                const float* __restrict__ W3, const float* __restrict__ b3,
                float* __restrict__ out) {
    extern __shared__ float sm[];
    float* sact = sm;
    float* sw1t = sm + W1T_OFF;
    float* scst = sm + CONST_OFF;
    const int tid = threadIdx.x;
    const int b   = blockIdx.x;

    // stage activations (straight blocked copy, conflict-free)
    {
        const float4* src = (const float4*)(g_out + (size_t)b * NGRP * (4 * NT));
        for (int i = tid; i < NGRP * 500; i += 512) {
            int g = i / 500, p = i % 500;
            *(float4*)(sact + g * GSTR + p * 4) = src[i];
        }
    }
    // stage W1 transposed (writes stride 501 -> conflict-free)
    for (int i = tid; i < NT * NH1; i += 512) {
        int j = i / NH1, k = i % NH1;
        sw1t[k * W1TS + j] = W1[i];
    }
    // small constants
    for (int i = tid; i < NH1 * NH2; i += 512) scst[i] = W2[i];
    if (tid < NH1) scst[500 + tid] = b1[tid];
    if (tid < NH2) scst[550 + tid] = b2[tid];
    if (tid < NH2) scst[560 + tid] = W3[tid];
    if (tid == 0)  scst[570] = b3[0];
    __syncthreads();

    // ---- layer 1: 8 rows x 5 k per thread, FFMA2 row-paired ----
    ull acc[4][5] = {};
    const bool active = tid < TILES * NSEG;   // 480
    int rt = 0, kt = 0, seg = 0;
    if (active) {
        seg = tid / TILES;
        int tile = tid % TILES;
        rt = tile & 7;
        kt = tile >> 3;
        int j0 = seg * 84;
        int j1 = min(j0 + 84, NT);
        const ulonglong2* oa = (const ulonglong2*)(sact + rt * GSTR);        // group rt
        const ulonglong2* obp = (const ulonglong2*)(sact + (rt + 8) * GSTR); // group rt+8
        const float* wk = sw1t + kt * 5 * W1TS;
        #pragma unroll 2
        for (int j = j0; j < j1; j++) {
            ulonglong2 a  = oa[j];
            ulonglong2 bb = obp[j];
            #pragma unroll
            for (int kk = 0; kk < 5; kk++) {
                ull wp = splat(wk[kk * W1TS + j]);
                acc[0][kk] = f2fma(a.x,  wp, acc[0][kk]);
                acc[1][kk] = f2fma(a.y,  wp, acc[1][kk]);
                acc[2][kk] = f2fma(bb.x, wp, acc[2][kk]);
                acc[3][kk] = f2fma(bb.y, wp, acc[3][kk]);
            }
        }
    }
    __syncthreads();   // all smem reads done

    // partials over dead W1T area: [seg][row][k]
    float* spart = sm + W1T_OFF;
    if (active) {
        #pragma unroll
        for (int p = 0; p < 4; p++) {
            int row = 4 * rt + (p & 1) * 2 + (p >> 1) * 32;
            #pragma unroll
            for (int kk = 0; kk < 5; kk++) {
                float lo, hi;
                unpack2(acc[p][kk], lo, hi);
                int k = kt * 5 + kk;
                spart[seg * (MROWS * NH1) + row * NH1 + k]       = lo;
                spart[seg * (MROWS * NH1) + (row + 1) * NH1 + k] = hi;
            }
        }
    }
    __syncthreads();

    // reduce partials + bias + leaky -> sh1 (overlays dead act area)
    float* sh1 = sm;
    for (int i = tid; i < MROWS * NH1; i += 512) {
        float s = spart[i];
        #pragma unroll
        for (int q = 1; q < NSEG; q++) s += spart[q * (MROWS * NH1) + i];
        s += scst[500 + (i % NH1)];
        sh1[i] = (s >= 0.0f) ? s : 0.01f * s;
    }
    __syncthreads();

    // layer 2
    float* sh2 = sm + 4096;
    for (int i = tid; i < MROWS * NH2; i += 512) {
        int r = i / NH2, kk = i % NH2;
        float a = scst[550 + kk];
        #pragma unroll
        for (int k = 0; k < NH1; k++)
            a = fmaf(sh1[r * NH1 + k], scst[k * NH2 + kk], a);
        sh2[i] = (a >= 0.0f) ? a : 0.01f * a;
    }
    __syncthreads();

    // layer 3
    if (tid < MROWS) {
        float a = scst[570];
        #pragma unroll
        for (int i = 0; i < NH2; i++)
            a = fmaf(sh2[tid * NH2 + i], scst[560 + i], a);
        out[b * MROWS + tid] = a;
    }
}

// keep 3 launches/call so the profiler's fixed launch slot lands on spline_kernel
__global__ void pad_kernel() {}

// =================== launch ===================================================
extern "C" void kernel_launch(void* const* d_in, const int* in_sizes, int n_in,
                              void* d_out, int out_size) {
    const float* x  = (const float*)d_in[0];
    const float* ri = (const float*)d_in[1];
    const float* W1 = (const float*)d_in[2];
    const float* b1 = (const float*)d_in[3];
    const float* W2 = (const float*)d_in[4];
    const float* b2 = (const float*)d_in[5];
    const float* W3 = (const float*)d_in[6];
    const float* b3 = (const float*)d_in[7];
    float* out = (float*)d_out;

    size_t smem1 = (size_t)SMEM_SPL_FL * sizeof(float);   // 74,064 B
    size_t smem2 = (size_t)SMEM_MLP_FL * sizeof(float);   // 231,784 B
    cudaFuncSetAttribute(spline_kernel, cudaFuncAttributeMaxDynamicSharedMemorySize, (int)smem1);
    cudaFuncSetAttribute(mlp_kernel,    cudaFuncAttributeMaxDynamicSharedMemorySize, (int)smem2);

    spline_kernel<<<BATCH / 4, 256, smem1>>>(x, ri);
    mlp_kernel<<<BATCH / MROWS, 512, smem2>>>(W1, b1, W2, b2, W3, b3, out);
    pad_kernel<<<1, 32>>>();
}

// round 6
// speedup vs baseline: 4.0669x; 1.1143x over previous
#include <cuda_runtime.h>
#include <math.h>

#define BATCH 8192
#define NKNOT 2000
#define NI    1999
#define NT    500
#define NH1   50
#define NH2   10
#define HALO  12
#define CSZ   17
#define NCH   118            // 117*17 = 1989, last chunk = 11

// spline smem layout (floats)
#define PSTR      4004
#define SKD_OFF   (2 * PSTR)              // 8008
#define SEV_OFF   (4 * PSTR)              // 16016
#define SPJ_OFF   (SEV_OFF + 4 * NT)      // 18016
#define SMEM_SPL_FL (SPJ_OFF + NT)        // 18516 -> 74,064 B (3 blocks/SM)

// MLP config (unchanged)
#define MROWS 64
#define NGRP  16
#define GSTR  2020
#define W1TS  501
#define NSEG  6
#define TILES 80
#define ACT_FL     (NGRP * GSTR)
#define W1T_OFF    ACT_FL
#define W1T_FL     (NH1 * W1TS)
#define CONST_OFF  (W1T_OFF + W1T_FL)
#define SMEM_MLP_FL (CONST_OFF + 576)

__constant__ float CP_TAB[8] = {
    0.5f, 0.28571429f, 0.26923077f, 0.26804124f,
    0.26795580f, 0.26794967f, 0.26794923f, 0.26794919f
};
#define CSTAR  0.26794919f
#define ELAST  0.57735027f
#define PW     5997.0f
#define WGC    (PW * CSTAR)
#define WGL    (PW * ELAST)

typedef unsigned long long ull;

__device__ float g_out[(size_t)BATCH * NT];   // blocked [2048 blk][500 j][4 rows]

__device__ __forceinline__ ull f2fma(ull a, ull b, ull c) {
    ull d; asm("fma.rn.f32x2 %0, %1, %2, %3;" : "=l"(d) : "l"(a), "l"(b), "l"(c)); return d;
}
__device__ __forceinline__ ull f2mul(ull a, ull b) {
    ull d; asm("mul.rn.f32x2 %0, %1, %2;" : "=l"(d) : "l"(a), "l"(b)); return d;
}
__device__ __forceinline__ ull f2add(ull a, ull b) {
    ull d; asm("add.rn.f32x2 %0, %1, %2;" : "=l"(d) : "l"(a), "l"(b)); return d;
}
__device__ __forceinline__ ull splat(float w) {
    ull r; asm("mov.b64 %0, {%1, %1};" : "=l"(r) : "f"(w)); return r;
}
__device__ __forceinline__ void unpack2(ull v, float& lo, float& hi) {
    asm("mov.b64 {%0, %1}, %2;" : "=f"(lo), "=f"(hi) : "l"(v));
}
__device__ __forceinline__ float tknot(int i) {
    return (i >= NI) ? 1.0f : (float)i * (1.0f / 1999.0f);
}

// =================== K1: fused spline solve + evaluate (f32x2) ===============
__global__ __launch_bounds__(256, 3)
void spline_kernel(const float* __restrict__ x, const float* __restrict__ raw_index) {
    extern __shared__ float sm[];
    float*  sxp  = sm;
    float*  skdp = sm + SKD_OFF;
    float4* sev  = (float4*)(sm + SEV_OFF);
    int*    spj  = (int*)(sm + SPJ_OFF);
    const int b0  = blockIdx.x * 4;
    const int tid = threadIdx.x;

    // ---- issue staging loads first (register-staged; hides DRAM latency) ----
    float4 va[4], vb[4];
    int pidx[4], qidx[4];
    #pragma unroll
    for (int k = 0; k < 4; k++) {
        int it = tid + k * 256;
        if (it < 1000) {
            int pr = it / 500, q = it - pr * 500;
            pidx[k] = pr; qidx[k] = q;
            va[k] = ((const float4*)(x + (size_t)(b0 + 2 * pr)     * NKNOT))[q];
            vb[k] = ((const float4*)(x + (size_t)(b0 + 2 * pr + 1) * NKNOT))[q];
        } else pidx[k] = -1;
    }

    // ---- eval-point preprocessing under the LDG latency ----
    for (int j = tid; j < NT; j += 256) {
        float z = raw_index[j];
        float t = 1.0f / (1.0f + expf(-z));
        int p = (int)(t * 1999.0f);
        if (p < 0) p = 0;
        if (p > 1998) p = 1998;
        while (p < 1998 && tknot(p + 1) < t) p++;
        while (p > 0 && tknot(p) >= t) p--;
        float tp  = tknot(p);
        float Hh  = tknot(p + 1) - tp;
        float u   = (t - tp) / Hh;
        float cb  = u * u * (3.0f - 2.0f * u);
        float omu = 1.0f - u;
        float4 c;
        c.x = 1.0f - cb;
        c.y = cb;
        c.z = Hh * u * omu * omu;
        c.w = Hh * u * u * (u - 1.0f);
        spj[j] = p;
        sev[j] = c;
    }

    // ---- interleaved STS ----
    #pragma unroll
    for (int k = 0; k < 4; k++) {
        if (pidx[k] >= 0) {
            float4 a = va[k], b = vb[k];
            float4* d = (float4*)(sxp + pidx[k] * PSTR + qidx[k] * 8);
            d[0] = make_float4(a.x, b.x, a.y, b.y);
            d[1] = make_float4(a.z, b.z, a.w, b.w);
        }
    }
    __syncthreads();

    // ---- chunked Thomas solve: 2 pairs x 118 chunks = 236 active threads ----
    if (tid < 2 * NCH) {
        const int pr = (tid >= NCH) ? 1 : 0;
        const int ch = tid - pr * NCH;
        const int c0 = ch * CSZ;
        const ull* X = (const ull*)(sxp  + pr * PSTR);
        ull*       K = (ull*)      (skdp + pr * PSTR);

        const ull NEG1 = splat(-1.0f);
        const ull CW   = splat(WGC);
        const ull CN   = splat(-CSTAR);

        ull dp = 0ULL, xm, xc, xn = 0ULL;

        if (ch == 0) {
            // forward i = 0..16 with exact table
            ull pp = 0ULL;
            xc = X[0];
            #pragma unroll
            for (int i = 0; i < CSZ; i++) {
                ull xp = X[i + 1];
                ull pc = f2mul(f2fma(xc, NEG1, xp), splat(PW));
                ull s  = f2add(pp, pc);
                if (i == 0) dp = f2mul(s, splat(0.5f));
                else        dp = f2mul(f2fma(dp, NEG1, s), splat((i < 8) ? CP_TAB[i] : CSTAR));
                K[i] = dp;
                pp = pc; xc = xp;
            }
            xm = X[CSZ - 1];
            // right halo (interior, i = 17..28)
            ull halo[HALO];
            #pragma unroll
            for (int k = 0; k < HALO; k++) {
                ull xp = X[CSZ + k + 1];
                dp = f2fma(dp, CN, f2mul(f2fma(xm, NEG1, xp), CW));
                halo[k] = dp; xm = xc; xc = xp;
            }
            #pragma unroll
            for (int k = HALO - 1; k >= 0; k--) xn = f2fma(xn, CN, halo[k]);
            // backward i = 16..0 with exact table
            #pragma unroll
            for (int i = CSZ - 1; i >= 0; i--) {
                xn = f2fma(xn, splat(-((i < 8) ? CP_TAB[i] : CSTAR)), K[i]);
                K[i] = xn;
            }
        } else if (ch < 116) {
            // left halo i = c0-12..c0-1
            xm = X[c0 - HALO - 1]; xc = X[c0 - HALO];
            #pragma unroll
            for (int k = 0; k < HALO; k++) {
                ull xp = X[c0 - HALO + k + 1];
                dp = f2fma(dp, CN, f2mul(f2fma(xm, NEG1, xp), CW));
                xm = xc; xc = xp;
            }
            // main i = c0..c0+16
            #pragma unroll
            for (int k = 0; k < CSZ; k++) {
                ull xp = X[c0 + k + 1];
                dp = f2fma(dp, CN, f2mul(f2fma(xm, NEG1, xp), CW));
                K[c0 + k] = dp;
                xm = xc; xc = xp;
            }
            // right halo i = c1..c1+11 (all interior: c1+11 <= 1983)
            ull halo[HALO];
            #pragma unroll
            for (int k = 0; k < HALO; k++) {
                ull xp = X[c0 + CSZ + k + 1];
                dp = f2fma(dp, CN, f2mul(f2fma(xm, NEG1, xp), CW));
                halo[k] = dp; xm = xc; xc = xp;
            }
            #pragma unroll
            for (int k = HALO - 1; k >= 0; k--) xn = f2fma(xn, CN, halo[k]);
            // backward main
            #pragma unroll
            for (int k = CSZ - 1; k >= 0; k--) {
                xn = f2fma(xn, CN, K[c0 + k]);
                K[c0 + k] = xn;
            }
        } else if (ch == 116) {
            // c0 = 1972, c1 = 1989; right halo clipped: i = 1989..1998 interior + 1999 ELAST
            xm = X[c0 - HALO - 1]; xc = X[c0 - HALO];
            #pragma unroll
            for (int k = 0; k < HALO; k++) {
                ull xp = X[c0 - HALO + k + 1];
                dp = f2fma(dp, CN, f2mul(f2fma(xm, NEG1, xp), CW));
                xm = xc; xc = xp;
            }
            #pragma unroll
            for (int k = 0; k < CSZ; k++) {
                ull xp = X[c0 + k + 1];
                dp = f2fma(dp, CN, f2mul(f2fma(xm, NEG1, xp), CW));
                K[c0 + k] = dp;
                xm = xc; xc = xp;
            }
            ull halo[11];
            #pragma unroll
            for (int k = 0; k < 10; k++) {       // i = 1989..1998
                ull xp = X[1990 + k];
                dp = f2fma(dp, CN, f2mul(f2fma(xm, NEG1, xp), CW));
                halo[k] = dp; xm = xc; xc = xp;
            }
            dp = f2fma(dp, splat(-ELAST), f2mul(f2fma(xm, NEG1, xc), splat(WGL))); // i=1999
            halo[10] = dp;
            xn = halo[10];                       // cp[1999] = 0
            #pragma unroll
            for (int k = 9; k >= 0; k--) xn = f2fma(xn, CN, halo[k]);
            #pragma unroll
            for (int k = CSZ - 1; k >= 0; k--) {
                xn = f2fma(xn, CN, K[c0 + k]);
                K[c0 + k] = xn;
            }
        } else {
            // ch == 117: c0 = 1989, len 11 (i = 1989..1999), no right halo
            xm = X[c0 - HALO - 1]; xc = X[c0 - HALO];
            #pragma unroll
            for (int k = 0; k < HALO; k++) {
                ull xp = X[c0 - HALO + k + 1];
                dp = f2fma(dp, CN, f2mul(f2fma(xm, NEG1, xp), CW));
                xm = xc; xc = xp;
            }
            #pragma unroll
            for (int k = 0; k < 10; k++) {       // i = 1989..1998
                ull xp = X[1990 + k];
                dp = f2fma(dp, CN, f2mul(f2fma(xm, NEG1, xp), CW));
                K[1989 + k] = dp;
                xm = xc; xc = xp;
            }
            dp = f2fma(dp, splat(-ELAST), f2mul(f2fma(xm, NEG1, xc), splat(WGL)));
            K[NI] = dp;
            xn = dp;
            #pragma unroll
            for (int k = 9; k >= 0; k--) {
                xn = f2fma(xn, CN, K[1989 + k]);
                K[1989 + k] = xn;
            }
        }
    }
    __syncthreads();

    // ---- evaluate: 1000 f32x2 items, blocked output [blk][j][4rows] ----
    float* ob = g_out + (size_t)blockIdx.x * (4 * NT);
    #pragma unroll
    for (int k = 0; k < 4; k++) {
        int it = tid + k * 256;
        if (it < 1000) {
            int j  = it >> 1;
            int pr = it & 1;
            int    p = spj[j];
            float4 c = sev[j];
            const ull* X = (const ull*)(sxp  + pr * PSTR);
            const ull* K = (const ull*)(skdp + pr * PSTR);
            ull r = f2mul(X[p], splat(c.x));
            r = f2fma(X[p + 1], splat(c.y), r);
            r = f2fma(K[p],     splat(c.z), r);
            r = f2fma(K[p + 1], splat(c.w), r);
            *(ull*)(ob + it * 2) = r;
        }
    }
}

// =================== K2: blocked weight-stationary MLP (unchanged) ===========
__global__ __launch_bounds__(512, 1)
void mlp_kernel(const float* __restrict__ W1, const float* __restrict__ b1,
                const float* __restrict__ W2, const float* __restrict__ b2,
                const float* __restrict__ W3, const float* __restrict__ b3,
                float* __restrict__ out) {
    extern __shared__ float sm[];
    float* sact = sm;
    float* sw1t = sm + W1T_OFF;
    float* scst = sm + CONST_OFF;
    const int tid = threadIdx.x;
    const int b   = blockIdx.x;

    {
        const float4* src = (const float4*)(g_out + (size_t)b * NGRP * (4 * NT));
        for (int i = tid; i < NGRP * 500; i += 512) {
            int g = i / 500, p = i % 500;
            *(float4*)(sact + g * GSTR + p * 4) = src[i];
        }
    }
    for (int i = tid; i < NT * NH1; i += 512) {
        int j = i / NH1, k = i % NH1;
        sw1t[k * W1TS + j] = W1[i];
    }
    for (int i = tid; i < NH1 * NH2; i += 512) scst[i] = W2[i];
    if (tid < NH1) scst[500 + tid] = b1[tid];
    if (tid < NH2) scst[550 + tid] = b2[tid];
    if (tid < NH2) scst[560 + tid] = W3[tid];
    if (tid == 0)  scst[570] = b3[0];
    __syncthreads();

    ull acc[4][5] = {};
    const bool active = tid < TILES * NSEG;
    int rt = 0, kt = 0, seg = 0;
    if (active) {
        seg = tid / TILES;
        int tile = tid % TILES;
        rt = tile & 7;
        kt = tile >> 3;
        int j0 = seg * 84;
        int j1 = min(j0 + 84, NT);
        const ulonglong2* oa  = (const ulonglong2*)(sact + rt * GSTR);
        const ulonglong2* obp = (const ulonglong2*)(sact + (rt + 8) * GSTR);
        const float* wk = sw1t + kt * 5 * W1TS;
        #pragma unroll 2
        for (int j = j0; j < j1; j++) {
            ulonglong2 a  = oa[j];
            ulonglong2 bb = obp[j];
            #pragma unroll
            for (int kk = 0; kk < 5; kk++) {
                ull wp = splat(wk[kk * W1TS + j]);
                acc[0][kk] = f2fma(a.x,  wp, acc[0][kk]);
                acc[1][kk] = f2fma(a.y,  wp, acc[1][kk]);
                acc[2][kk] = f2fma(bb.x, wp, acc[2][kk]);
                acc[3][kk] = f2fma(bb.y, wp, acc[3][kk]);
            }
        }
    }
    __syncthreads();

    float* spart = sm + W1T_OFF;
    if (active) {
        #pragma unroll
        for (int p = 0; p < 4; p++) {
            int row = 4 * rt + (p & 1) * 2 + (p >> 1) * 32;
            #pragma unroll
            for (int kk = 0; kk < 5; kk++) {
                float lo, hi;
                unpack2(acc[p][kk], lo, hi);
                int k = kt * 5 + kk;
                spart[seg * (MROWS * NH1) + row * NH1 + k]       = lo;
                spart[seg * (MROWS * NH1) + (row + 1) * NH1 + k] = hi;
            }
        }
    }
    __syncthreads();

    float* sh1 = sm;
    for (int i = tid; i < MROWS * NH1; i += 512) {
        float s = spart[i];
        #pragma unroll
        for (int q = 1; q < NSEG; q++) s += spart[q * (MROWS * NH1) + i];
        s += scst[500 + (i % NH1)];
        sh1[i] = (s >= 0.0f) ? s : 0.01f * s;
    }
    __syncthreads();

    float* sh2 = sm + 4096;
    for (int i = tid; i < MROWS * NH2; i += 512) {
        int r = i / NH2, kk = i % NH2;
        float a = scst[550 + kk];
        #pragma unroll
        for (int k = 0; k < NH1; k++)
            a = fmaf(sh1[r * NH1 + k], scst[k * NH2 + kk], a);
        sh2[i] = (a >= 0.0f) ? a : 0.01f * a;
    }
    __syncthreads();

    if (tid < MROWS) {
        float a = scst[570];
        #pragma unroll
        for (int i = 0; i < NH2; i++)
            a = fmaf(sh2[tid * NH2 + i], scst[560 + i], a);
        out[b * MROWS + tid] = a;
    }
}

// =================== launch ===================================================
extern "C" void kernel_launch(void* const* d_in, const int* in_sizes, int n_in,
                              void* d_out, int out_size) {
    const float* x  = (const float*)d_in[0];
    const float* ri = (const float*)d_in[1];
    const float* W1 = (const float*)d_in[2];
    const float* b1 = (const float*)d_in[3];
    const float* W2 = (const float*)d_in[4];
    const float* b2 = (const float*)d_in[5];
    const float* W3 = (const float*)d_in[6];
    const float* b3 = (const float*)d_in[7];
    float* out = (float*)d_out;

    size_t smem1 = (size_t)SMEM_SPL_FL * sizeof(float);   // 74,064 B
    size_t smem2 = (size_t)SMEM_MLP_FL * sizeof(float);   // 231,784 B
    cudaFuncSetAttribute(spline_kernel, cudaFuncAttributeMaxDynamicSharedMemorySize, (int)smem1);
    cudaFuncSetAttribute(mlp_kernel,    cudaFuncAttributeMaxDynamicSharedMemorySize, (int)smem2);

    spline_kernel<<<BATCH / 4, 256, smem1>>>(x, ri);
    mlp_kernel<<<BATCH / MROWS, 512, smem2>>>(W1, b1, W2, b2, W3, b3, out);
}

// round 8
// speedup vs baseline: 4.2272x; 1.0394x over previous
#include <cuda_runtime.h>
#include <math.h>

#define BATCH 8192
#define NKNOT 2000
#define NI    1999
#define NT    500
#define NH1   50
#define NH2   10
#define HALO  12
#define CSZ   17
#define NCH   118            // 117*17 = 1989, last chunk = 11

// spline smem layout (floats)
#define PSTR      4004
#define SKD_OFF   (2 * PSTR)
#define SEV_OFF   (4 * PSTR)
#define SPJ_OFF   (SEV_OFF + 4 * NT)
#define SMEM_SPL_FL (SPJ_OFF + NT)        // 18516 -> 74,064 B (3 blocks/SM)

// MLP config
#define MROWS 64
#define NGRP  16
#define GSTR  2020
#define NSEG  6
#define TILES 160                          // 16 row-groups x 10 k-tiles
#define PSTRD (MROWS * NH1)                // 3200
#define ACT_FL     (NGRP * GSTR)           // 32320
#define W1_OFF     ACT_FL                  // dense W1 [j][k]
#define W1_FL      (NT * NH1)              // 25000
#define CONST_OFF  (W1_OFF + W1_FL)        // 57320
#define SMEM_MLP_FL (CONST_OFF + 576)      // 57896 -> 231,584 B
#define SH1_OFF    20000                   // after partials (6*3200 = 19200)
#define SH2_OFF    24000

__constant__ float CP_TAB[8] = {
    0.5f, 0.28571429f, 0.26923077f, 0.26804124f,
    0.26795580f, 0.26794967f, 0.26794923f, 0.26794919f
};
#define CSTAR  0.26794919f
#define ELAST  0.57735027f
#define PW     5997.0f
#define WGC    (PW * CSTAR)
#define WGL    (PW * ELAST)

typedef unsigned long long ull;

__device__ float g_out[(size_t)BATCH * NT];   // blocked [2048 blk][500 j][4 rows]

__device__ __forceinline__ ull f2fma(ull a, ull b, ull c) {
    ull d; asm("fma.rn.f32x2 %0, %1, %2, %3;" : "=l"(d) : "l"(a), "l"(b), "l"(c)); return d;
}
__device__ __forceinline__ ull f2mul(ull a, ull b) {
    ull d; asm("mul.rn.f32x2 %0, %1, %2;" : "=l"(d) : "l"(a), "l"(b)); return d;
}
__device__ __forceinline__ ull f2add(ull a, ull b) {
    ull d; asm("add.rn.f32x2 %0, %1, %2;" : "=l"(d) : "l"(a), "l"(b)); return d;
}
__device__ __forceinline__ ull splat(float w) {
    ull r; asm("mov.b64 %0, {%1, %1};" : "=l"(r) : "f"(w)); return r;
}
__device__ __forceinline__ void unpack2(ull v, float& lo, float& hi) {
    asm("mov.b64 {%0, %1}, %2;" : "=f"(lo), "=f"(hi) : "l"(v));
}
__device__ __forceinline__ float tknot(int i) {
    return (i >= NI) ? 1.0f : (float)i * (1.0f / 1999.0f);
}

// =================== K1: fused spline solve + evaluate (f32x2) ===============
__global__ __launch_bounds__(256, 3)
void spline_kernel(const float* __restrict__ x, const float* __restrict__ raw_index) {
    extern __shared__ float sm[];
    float*  sxp  = sm;
    float*  skdp = sm + SKD_OFF;
    float4* sev  = (float4*)(sm + SEV_OFF);
    int*    spj  = (int*)(sm + SPJ_OFF);
    const int b0  = blockIdx.x * 4;
    const int tid = threadIdx.x;

    float4 va[4], vb[4];
    int pidx[4], qidx[4];
    #pragma unroll
    for (int k = 0; k < 4; k++) {
        int it = tid + k * 256;
        if (it < 1000) {
            int pr = it / 500, q = it - pr * 500;
            pidx[k] = pr; qidx[k] = q;
            va[k] = ((const float4*)(x + (size_t)(b0 + 2 * pr)     * NKNOT))[q];
            vb[k] = ((const float4*)(x + (size_t)(b0 + 2 * pr + 1) * NKNOT))[q];
        } else pidx[k] = -1;
    }

    for (int j = tid; j < NT; j += 256) {
        float z = raw_index[j];
        float t = 1.0f / (1.0f + expf(-z));
        int p = (int)(t * 1999.0f);
        if (p < 0) p = 0;
        if (p > 1998) p = 1998;
        while (p < 1998 && tknot(p + 1) < t) p++;
        while (p > 0 && tknot(p) >= t) p--;
        float tp  = tknot(p);
        float Hh  = tknot(p + 1) - tp;
        float u   = (t - tp) / Hh;
        float cb  = u * u * (3.0f - 2.0f * u);
        float omu = 1.0f - u;
        float4 c;
        c.x = 1.0f - cb;
        c.y = cb;
        c.z = Hh * u * omu * omu;
        c.w = Hh * u * u * (u - 1.0f);
        spj[j] = p;
        sev[j] = c;
    }

    #pragma unroll
    for (int k = 0; k < 4; k++) {
        if (pidx[k] >= 0) {
            float4 a = va[k], b = vb[k];
            float4* d = (float4*)(sxp + pidx[k] * PSTR + qidx[k] * 8);
            d[0] = make_float4(a.x, b.x, a.y, b.y);
            d[1] = make_float4(a.z, b.z, a.w, b.w);
        }
    }
    __syncthreads();

    if (tid < 2 * NCH) {
        const int pr = (tid >= NCH) ? 1 : 0;
        const int ch = tid - pr * NCH;
        const int c0 = ch * CSZ;
        const ull* X = (const ull*)(sxp  + pr * PSTR);
        ull*       K = (ull*)      (skdp + pr * PSTR);

        const ull NEG1 = splat(-1.0f);
        const ull CW   = splat(WGC);
        const ull CN   = splat(-CSTAR);

        ull dp = 0ULL, xm, xc, xn = 0ULL;

        if (ch == 0) {
            ull pp = 0ULL;
            xc = X[0];
            #pragma unroll
            for (int i = 0; i < CSZ; i++) {
                ull xp = X[i + 1];
                ull pc = f2mul(f2fma(xc, NEG1, xp), splat(PW));
                ull s  = f2add(pp, pc);
                if (i == 0) dp = f2mul(s, splat(0.5f));
                else        dp = f2mul(f2fma(dp, NEG1, s), splat((i < 8) ? CP_TAB[i] : CSTAR));
                K[i] = dp;
                pp = pc; xc = xp;
            }
            xm = X[CSZ - 1];
            ull halo[HALO];
            #pragma unroll
            for (int k = 0; k < HALO; k++) {
                ull xp = X[CSZ + k + 1];
                dp = f2fma(dp, CN, f2mul(f2fma(xm, NEG1, xp), CW));
                halo[k] = dp; xm = xc; xc = xp;
            }
            #pragma unroll
            for (int k = HALO - 1; k >= 0; k--) xn = f2fma(xn, CN, halo[k]);
            #pragma unroll
            for (int i = CSZ - 1; i >= 0; i--) {
                xn = f2fma(xn, splat(-((i < 8) ? CP_TAB[i] : CSTAR)), K[i]);
                K[i] = xn;
            }
        } else if (ch < 116) {
            xm = X[c0 - HALO - 1]; xc = X[c0 - HALO];
            #pragma unroll
            for (int k = 0; k < HALO; k++) {
                ull xp = X[c0 - HALO + k + 1];
                dp = f2fma(dp, CN, f2mul(f2fma(xm, NEG1, xp), CW));
                xm = xc; xc = xp;
            }
            #pragma unroll
            for (int k = 0; k < CSZ; k++) {
                ull xp = X[c0 + k + 1];
                dp = f2fma(dp, CN, f2mul(f2fma(xm, NEG1, xp), CW));
                K[c0 + k] = dp;
                xm = xc; xc = xp;
            }
            ull halo[HALO];
            #pragma unroll
            for (int k = 0; k < HALO; k++) {
                ull xp = X[c0 + CSZ + k + 1];
                dp = f2fma(dp, CN, f2mul(f2fma(xm, NEG1, xp), CW));
                halo[k] = dp; xm = xc; xc = xp;
            }
            #pragma unroll
            for (int k = HALO - 1; k >= 0; k--) xn = f2fma(xn, CN, halo[k]);
            #pragma unroll
            for (int k = CSZ - 1; k >= 0; k--) {
                xn = f2fma(xn, CN, K[c0 + k]);
                K[c0 + k] = xn;
            }
        } else if (ch == 116) {
            xm = X[c0 - HALO - 1]; xc = X[c0 - HALO];
            #pragma unroll
            for (int k = 0; k < HALO; k++) {
                ull xp = X[c0 - HALO + k + 1];
                dp = f2fma(dp, CN, f2mul(f2fma(xm, NEG1, xp), CW));
                xm = xc; xc = xp;
            }
            #pragma unroll
            for (int k = 0; k < CSZ; k++) {
                ull xp = X[c0 + k + 1];
                dp = f2fma(dp, CN, f2mul(f2fma(xm, NEG1, xp), CW));
                K[c0 + k] = dp;
                xm = xc; xc = xp;
            }
            ull halo[11];
            #pragma unroll
            for (int k = 0; k < 10; k++) {
                ull xp = X[1990 + k];
                dp = f2fma(dp, CN, f2mul(f2fma(xm, NEG1, xp), CW));
                halo[k] = dp; xm = xc; xc = xp;
            }
            dp = f2fma(dp, splat(-ELAST), f2mul(f2fma(xm, NEG1, xc), splat(WGL)));
            halo[10] = dp;
            xn = halo[10];
            #pragma unroll
            for (int k = 9; k >= 0; k--) xn = f2fma(xn, CN, halo[k]);
            #pragma unroll
            for (int k = CSZ - 1; k >= 0; k--) {
                xn = f2fma(xn, CN, K[c0 + k]);
                K[c0 + k] = xn;
            }
        } else {
            xm = X[c0 - HALO - 1]; xc = X[c0 - HALO];
            #pragma unroll
            for (int k = 0; k < HALO; k++) {
                ull xp = X[c0 - HALO + k + 1];
                dp = f2fma(dp, CN, f2mul(f2fma(xm, NEG1, xp), CW));
                xm = xc; xc = xp;
            }
            #pragma unroll
            for (int k = 0; k < 10; k++) {
                ull xp = X[1990 + k];
                dp = f2fma(dp, CN, f2mul(f2fma(xm, NEG1, xp), CW));
                K[1989 + k] = dp;
                xm = xc; xc = xp;
            }
            dp = f2fma(dp, splat(-ELAST), f2mul(f2fma(xm, NEG1, xc), splat(WGL)));
            K[NI] = dp;
            xn = dp;
            #pragma unroll
            for (int k = 9; k >= 0; k--) {
                xn = f2fma(xn, CN, K[1989 + k]);
                K[1989 + k] = xn;
            }
        }
    }
    __syncthreads();

    float* ob = g_out + (size_t)blockIdx.x * (4 * NT);
    #pragma unroll
    for (int k = 0; k < 4; k++) {
        int it = tid + k * 256;
        if (it < 1000) {
            int j  = it >> 1;
            int pr = it & 1;
            int    p = spj[j];
            float4 c = sev[j];
            const ull* X = (const ull*)(sxp  + pr * PSTR);
            const ull* K = (const ull*)(skdp + pr * PSTR);
            ull r = f2mul(X[p], splat(c.x));
            r = f2fma(X[p + 1], splat(c.y), r);
            r = f2fma(K[p],     splat(c.z), r);
            r = f2fma(K[p + 1], splat(c.w), r);
            *(ull*)(ob + it * 2) = r;
        }
    }
}

// =================== K2: blocked weight-stationary MLP (v3, fixed) ===========
__global__ __launch_bounds__(1024, 1)
void mlp_kernel(const float* __restrict__ W1, const float* __restrict__ b1,
                const float* __restrict__ W2, const float* __restrict__ b2,
                const float* __restrict__ W3, const float* __restrict__ b3,
                float* __restrict__ out) {
    extern __shared__ float sm[];
    float* sact = sm;                    // 16 groups x 2020
    float* sw1  = sm + W1_OFF;           // dense W1 [j][k] (k contiguous)
    float* scst = sm + CONST_OFF;
    const int tid = threadIdx.x;
    const int b   = blockIdx.x;

    // stage activations (straight blocked copy)
    {
        const float4* src = (const float4*)(g_out + (size_t)b * NGRP * (4 * NT));
        #pragma unroll
        for (int k = 0; k < 8; k++) {
            int i = tid + k * 1024;
            if (i < NGRP * 500) {
                int g = i / 500, p = i - g * 500;
                *(float4*)(sact + g * GSTR + p * 4) = src[i];
            }
        }
    }
    // stage W1 dense (no transpose)
    {
        const float4* w4 = (const float4*)W1;
        #pragma unroll
        for (int k = 0; k < 7; k++) {
            int i = tid + k * 1024;
            if (i < W1_FL / 4) *(float4*)(sw1 + i * 4) = w4[i];
        }
    }
    for (int i = tid; i < NH1 * NH2; i += 1024) scst[i] = W2[i];
    if (tid < NH1) scst[500 + tid] = b1[tid];
    if (tid < NH2) scst[550 + tid] = b2[tid];
    if (tid < NH2) scst[560 + tid] = W3[tid];
    if (tid == 0)  scst[570] = b3[0];
    __syncthreads();

    // ---- layer 1: 4 rows (one group) x 5 k per thread, 960 active ----
    ull acc[2][5] = {};
    const bool active = tid < TILES * NSEG;   // 960
    int rt = 0, kt = 0, seg = 0;
    if (active) {
        seg = tid / TILES;
        int tile = tid - seg * TILES;
        rt = tile & 15;            // row-group 0..15
        kt = tile >> 4;            // k-tile   0..9
        int j0 = seg * 84;
        int j1 = min(j0 + 84, NT);
        const ulonglong2* oa = (const ulonglong2*)(sact + rt * GSTR);
        const float* wb = sw1 + kt * 5;
        #pragma unroll 4
        for (int j = j0; j < j1; j++) {
            ulonglong2 a = oa[j];
            const float* wj = wb + j * NH1;
            // scalar weight loads (broadcast within warp; float4 here would
            // be misaligned: kt*5 floats is not 16B-aligned for most kt)
            ull wp0 = splat(wj[0]);
            ull wp1 = splat(wj[1]);
            ull wp2 = splat(wj[2]);
            ull wp3 = splat(wj[3]);
            ull wp4 = splat(wj[4]);
            acc[0][0] = f2fma(a.x, wp0, acc[0][0]);
            acc[1][0] = f2fma(a.y, wp0, acc[1][0]);
            acc[0][1] = f2fma(a.x, wp1, acc[0][1]);
            acc[1][1] = f2fma(a.y, wp1, acc[1][1]);
            acc[0][2] = f2fma(a.x, wp2, acc[0][2]);
            acc[1][2] = f2fma(a.y, wp2, acc[1][2]);
            acc[0][3] = f2fma(a.x, wp3, acc[0][3]);
            acc[1][3] = f2fma(a.y, wp3, acc[1][3]);
            acc[0][4] = f2fma(a.x, wp4, acc[0][4]);
            acc[1][4] = f2fma(a.y, wp4, acc[1][4]);
        }
    }
    __syncthreads();   // all smem reads done; act+W1 regions now dead

    // partials overlay: [seg][row][k] at sm[0..19200)
    float* spart = sm;
    if (active) {
        #pragma unroll
        for (int p = 0; p < 2; p++) {
            int row = 4 * rt + 2 * p;
            #pragma unroll
            for (int kk = 0; kk < 5; kk++) {
                float lo, hi;
                unpack2(acc[p][kk], lo, hi);
                int k = kt * 5 + kk;
                spart[seg * PSTRD + row * NH1 + k]       = lo;
                spart[seg * PSTRD + (row + 1) * NH1 + k] = hi;
            }
        }
    }
    __syncthreads();

    // reduce partials + bias + leaky -> sh1
    float* sh1 = sm + SH1_OFF;
    #pragma unroll
    for (int k = 0; k < 4; k++) {
        int i = tid + k * 1024;
        if (i < PSTRD) {
            float s = spart[i];
            #pragma unroll
            for (int q = 1; q < NSEG; q++) s += spart[q * PSTRD + i];
            s += scst[500 + (i % NH1)];
            sh1[i] = (s >= 0.0f) ? s : 0.01f * s;
        }
    }
    __syncthreads();

    // layer 2: 640 outputs, one per thread
    float* sh2 = sm + SH2_OFF;
    if (tid < MROWS * NH2) {
        int r = tid / NH2, kk = tid - r * NH2;
        float a = scst[550 + kk];
        #pragma unroll
        for (int k = 0; k < NH1; k++)
            a = fmaf(sh1[r * NH1 + k], scst[k * NH2 + kk], a);
        sh2[tid] = (a >= 0.0f) ? a : 0.01f * a;
    }
    __syncthreads();

    // layer 3
    if (tid < MROWS) {
        float a = scst[570];
        #pragma unroll
        for (int i = 0; i < NH2; i++)
            a = fmaf(sh2[tid * NH2 + i], scst[560 + i], a);
        out[b * MROWS + tid] = a;
    }
}

// =================== launch ===================================================
extern "C" void kernel_launch(void* const* d_in, const int* in_sizes, int n_in,
                              void* d_out, int out_size) {
    const float* x  = (const float*)d_in[0];
    const float* ri = (const float*)d_in[1];
    const float* W1 = (const float*)d_in[2];
    const float* b1 = (const float*)d_in[3];
    const float* W2 = (const float*)d_in[4];
    const float* b2 = (const float*)d_in[5];
    const float* W3 = (const float*)d_in[6];
    const float* b3 = (const float*)d_in[7];
    float* out = (float*)d_out;

    size_t smem1 = (size_t)SMEM_SPL_FL * sizeof(float);   // 74,064 B
    size_t smem2 = (size_t)SMEM_MLP_FL * sizeof(float);   // 231,584 B
    cudaFuncSetAttribute(spline_kernel, cudaFuncAttributeMaxDynamicSharedMemorySize, (int)smem1);
    cudaFuncSetAttribute(mlp_kernel,    cudaFuncAttributeMaxDynamicSharedMemorySize, (int)smem2);

    spline_kernel<<<BATCH / 4, 256, smem1>>>(x, ri);
    mlp_kernel<<<BATCH / MROWS, 1024, smem2>>>(W1, b1, W2, b2, W3, b3, out);
}